// round 16
// baseline (speedup 1.0000x reference)
#include <cuda_runtime.h>
#include <cuda_fp16.h>
#include <cstdint>

#define B_   4
#define S_   2048
#define DIN  1024
#define DOUT 1024
#define H_   16
#define HD_  64
#define KDIM 1024

// ---------------------------------------------------------------------------
// Scratch (module-scope device arrays: allowed; no runtime allocation)
// ---------------------------------------------------------------------------
__device__ __half g_Q[B_ * H_ * S_ * HD_];   // (b,h,s,hd), pre-scaled by 0.125*log2e
__device__ __half g_K[B_ * H_ * S_ * HD_];   // (b,h,s,hd)
__device__ __half g_V[B_ * H_ * S_ * HD_];   // (b,h,s,hd)
__device__ __half g_ctx[B_ * S_ * DOUT];     // (b,s,d)
__device__ __half g_WT[3 * DIN * DOUT];      // Wq^T,Wk^T,Wv^T [n][k]
__device__ __half g_X [B_ * S_ * DIN];       // x
__device__ __half g_Wo[DOUT * DOUT];         // Wo [n][k]

// ---------------------------------------------------------------------------
// helpers
// ---------------------------------------------------------------------------
__device__ __forceinline__ uint32_t pack_h2(float lo, float hi) {
    uint32_t d;
    asm("cvt.rn.f16x2.f32 %0, %1, %2;" : "=r"(d) : "f"(hi), "f"(lo));
    return d;
}
__device__ __forceinline__ float fexp2(float x) {
    float y;
    asm("ex2.approx.f32 %0, %1;" : "=f"(y) : "f"(x));
    return y;
}
__device__ __forceinline__ uint32_t smem_u32(const void* p) {
    uint32_t a;
    asm("{ .reg .u64 t; cvta.to.shared.u64 t, %1; cvt.u32.u64 %0, t; }"
        : "=r"(a) : "l"(p));
    return a;
}
__device__ __forceinline__ void cp16(uint32_t dst, const void* src) {
    asm volatile("cp.async.cg.shared.global [%0], [%1], 16;"
                 :: "r"(dst), "l"(src) : "memory");
}
#define CP_COMMIT() asm volatile("cp.async.commit_group;" ::: "memory")
#define CP_WAIT(n)  asm volatile("cp.async.wait_group %0;" :: "n"(n) : "memory")

__device__ __forceinline__ void ldsm_x4(uint32_t addr,
    uint32_t& r0, uint32_t& r1, uint32_t& r2, uint32_t& r3)
{
    asm volatile("ldmatrix.sync.aligned.m8n8.x4.shared.b16 {%0,%1,%2,%3}, [%4];"
        : "=r"(r0), "=r"(r1), "=r"(r2), "=r"(r3) : "r"(addr));
}
__device__ __forceinline__ void ldsm_x4_t(uint32_t addr,
    uint32_t& r0, uint32_t& r1, uint32_t& r2, uint32_t& r3)
{
    asm volatile("ldmatrix.sync.aligned.m8n8.x4.trans.shared.b16 {%0,%1,%2,%3}, [%4];"
        : "=r"(r0), "=r"(r1), "=r"(r2), "=r"(r3) : "r"(addr));
}

// D += A*B, m16n8k16 f16 inputs, fp32 accumulate
__device__ __forceinline__ void mma_f16(float* d,
    uint32_t a0, uint32_t a1, uint32_t a2, uint32_t a3,
    uint32_t b0, uint32_t b1)
{
    asm volatile(
        "mma.sync.aligned.m16n8k16.row.col.f32.f16.f16.f32 "
        "{%0,%1,%2,%3}, {%4,%5,%6,%7}, {%8,%9}, {%0,%1,%2,%3};"
        : "+f"(d[0]), "+f"(d[1]), "+f"(d[2]), "+f"(d[3])
        : "r"(a0), "r"(a1), "r"(a2), "r"(a3), "r"(b0), "r"(b1));
}

// ---------------------------------------------------------------------------
// Kernel P: fused prep.  Blocks [0, 9216): convert x->g_X, Wo->g_Wo (f16).
// Blocks [9216, 12288): transpose Wq/Wk/Wv ([K,N]->[N,K]) + f16 into g_WT.
// ---------------------------------------------------------------------------
#define XF4    (B_ * S_ * DIN / 4)              // 2097152
#define CVTBLK ((XF4 + DOUT * DOUT / 4) / 256)  // 9216
__global__ __launch_bounds__(256) void prep_kernel(
    const float* __restrict__ x,  const float* __restrict__ Wq,
    const float* __restrict__ Wk, const float* __restrict__ Wv,
    const float* __restrict__ Wo)
{
    __shared__ float t[32][33];
    const int tid = threadIdx.x;
    if ((int)blockIdx.x < CVTBLK) {
        int i = blockIdx.x * 256 + tid;
        if (i < XF4) {
            float4 v = *reinterpret_cast<const float4*>(x + (size_t)i * 4);
            uint2 r = {pack_h2(v.x, v.y), pack_h2(v.z, v.w)};
            reinterpret_cast<uint2*>(g_X)[i] = r;
        } else {
            int j = i - XF4;
            float4 v = *reinterpret_cast<const float4*>(Wo + (size_t)j * 4);
            uint2 r = {pack_h2(v.x, v.y), pack_h2(v.z, v.w)};
            reinterpret_cast<uint2*>(g_Wo)[j] = r;
        }
    } else {
        int tp = blockIdx.x - CVTBLK;     // 0..3071
        int z  = tp >> 10;                // weight index
        int r  = tp & 1023;
        int bx = (r & 31) * 32, by = (r >> 5) * 32;
        int tx = tid & 31, ty = tid >> 5; // (32, 8)
        const float* src = (z == 0) ? Wq : (z == 1) ? Wk : Wv;
        __half* dst = g_WT + (size_t)z * DIN * DOUT;
        #pragma unroll
        for (int i = 0; i < 32; i += 8)
            t[ty + i][tx] = src[(size_t)(by + ty + i) * DOUT + bx + tx];
        __syncthreads();
        #pragma unroll
        for (int i = 0; i < 32; i += 8)
            dst[(size_t)(bx + ty + i) * DIN + by + tx] = __float2half_rn(t[tx][ty + i]);
    }
}

// ---------------------------------------------------------------------------
// GEMM f16: C[128x128] = A[128xK] * B[128xK]^T, fp32 accum.
// 128 threads, 4 warps (2m x 2n), warp tile 64x64: halves smem bytes per MMA
// (4 MMA/KB vs 2).  2 CTAs/SM (regs ~180) so per-CTA barriers overlap.
// BK=64, 2-stage cp.async, ONE __syncthreads per chunk (issue after sync).
// ---------------------------------------------------------------------------
#define GPADH 72
#define GSTGB (128 * GPADH * 2)    // 18432 bytes / stage / matrix
#define NCH64 (KDIM / 64)          // 16 chunks

#define GEMM_ISSUE(ch, stage) do {                                           \
    _Pragma("unroll")                                                        \
    for (int i_ = 0; i_ < 8; ++i_) {                                         \
        int f_ = tid + i_ * 128, row_ = f_ >> 3, k8_ = f_ & 7;               \
        uint32_t off_ = (uint32_t)(stage) * GSTGB +                          \
                        (uint32_t)(row_ * GPADH + k8_ * 8) * 2u;             \
        cp16(uA + off_, Asrc + (size_t)row_ * KDIM + (ch) * 64 + k8_ * 8);   \
        cp16(uB + off_, Bsrc + (size_t)row_ * KDIM + (ch) * 64 + k8_ * 8);   \
    }                                                                        \
    CP_COMMIT();                                                             \
} while (0)

__device__ __forceinline__ void gemm_f16_mainloop(
    const __half* __restrict__ Asrc, const __half* __restrict__ Bsrc,
    uint32_t uA, uint32_t uB, float acc[4][8][4], int tid, int wm, int wn)
{
    const int lane = tid & 31;
    #pragma unroll
    for (int mt = 0; mt < 4; ++mt)
        #pragma unroll
        for (int nt = 0; nt < 8; ++nt)
            #pragma unroll
            for (int j = 0; j < 4; ++j) acc[mt][nt][j] = 0.0f;

    const uint32_t baseA = uA +
        (uint32_t)((wm * 64 + (lane & 15)) * GPADH + (lane >> 4) * 8) * 2u;
    const uint32_t baseB = uB +
        (uint32_t)((wn * 64 + (lane & 15)) * GPADH + (lane >> 4) * 8) * 2u;

    GEMM_ISSUE(0, 0);
    for (int ch = 0; ch < NCH64; ++ch) {
        CP_WAIT(0);
        __syncthreads();
        if (ch + 1 < NCH64) GEMM_ISSUE(ch + 1, (ch + 1) & 1);

        const uint32_t stg = (uint32_t)(ch & 1) * GSTGB;
        #pragma unroll
        for (int ks = 0; ks < 4; ++ks) {
            uint32_t a[4][4], b[8][2];
            #pragma unroll
            for (int mt = 0; mt < 4; ++mt)
                ldsm_x4(baseA + stg + (uint32_t)(mt * 16 * GPADH + ks * 16) * 2u,
                        a[mt][0], a[mt][1], a[mt][2], a[mt][3]);
            #pragma unroll
            for (int ntp = 0; ntp < 4; ++ntp) {
                uint32_t r0, r1, r2, r3;
                ldsm_x4(baseB + stg + (uint32_t)(ntp * 16 * GPADH + ks * 16) * 2u,
                        r0, r1, r2, r3);
                b[2 * ntp][0] = r0; b[2 * ntp][1] = r2;
                b[2 * ntp + 1][0] = r1; b[2 * ntp + 1][1] = r3;
            }
            #pragma unroll
            for (int mt = 0; mt < 4; ++mt)
                #pragma unroll
                for (int nt = 0; nt < 8; ++nt)
                    mma_f16(acc[mt][nt], a[mt][0], a[mt][1], a[mt][2], a[mt][3],
                            b[nt][0], b[nt][1]);
        }
    }
}

// ---------------------------------------------------------------------------
// Kernel 1: QKV projection.  grid (64, 24), 128 threads, dyn smem.
// Each warp's 64-wide N span lies in exactly one head.
// ---------------------------------------------------------------------------
__global__ __launch_bounds__(128, 2) void qkv_tc_kernel()
{
    extern __shared__ uint32_t dyn[];
    const uint32_t uA = smem_u32(dyn);
    const uint32_t uB = uA + 2 * GSTGB;

    const int tid = threadIdx.x;
    const int wid = tid >> 5, lane = tid & 31;
    const int g = lane >> 2, q = lane & 3;
    const int wm = wid >> 1, wn = wid & 1;    // 2m x 2n warps

    const int rowBase = blockIdx.x * 128;
    const int n0glob  = blockIdx.y * 128;
    const int w       = n0glob >> 10;
    const int nw      = n0glob & 1023;

    float acc[4][8][4];
    gemm_f16_mainloop(g_X + (size_t)rowBase * KDIM,
                      g_WT + (size_t)n0glob * KDIM,
                      uA, uB, acc, tid, wm, wn);

    __half* obuf = (w == 0) ? g_Q : (w == 1) ? g_K : g_V;
    const float scale = (w == 0) ? 0.125f * 1.4426950408889634f : 1.0f;
    const int h = (nw + wn * 64) >> 6;        // constant per warp
    #pragma unroll
    for (int mt = 0; mt < 4; ++mt) {
        int m0 = rowBase + wm * 64 + mt * 16 + g;
        int b0 = m0 >> 11, s0 = m0 & 2047;
        int m1 = m0 + 8;
        int b1 = m1 >> 11, s1 = m1 & 2047;
        __half* p0 = &obuf[(((size_t)(b0 * H_ + h) * S_) + s0) * HD_];
        __half* p1 = &obuf[(((size_t)(b1 * H_ + h) * S_) + s1) * HD_];
        #pragma unroll
        for (int nt = 0; nt < 8; ++nt) {
            int hd = nt * 8 + 2 * q;
            *reinterpret_cast<uint32_t*>(p0 + hd) =
                pack_h2(acc[mt][nt][0] * scale, acc[mt][nt][1] * scale);
            *reinterpret_cast<uint32_t*>(p1 + hd) =
                pack_h2(acc[mt][nt][2] * scale, acc[mt][nt][3] * scale);
        }
    }
}

// ---------------------------------------------------------------------------
// Kernel 3: output projection.  out = ctx @ Wo^T + bo (fp32 out).  grid (64, 8).
// ---------------------------------------------------------------------------
__global__ __launch_bounds__(128, 2) void oproj_tc_kernel(
    const float* __restrict__ bo, float* __restrict__ out)
{
    extern __shared__ uint32_t dyn[];
    const uint32_t uA = smem_u32(dyn);
    const uint32_t uB = uA + 2 * GSTGB;

    const int tid = threadIdx.x;
    const int wid = tid >> 5, lane = tid & 31;
    const int g = lane >> 2, q = lane & 3;
    const int wm = wid >> 1, wn = wid & 1;

    const int rowBase = blockIdx.x * 128;
    const int n0      = blockIdx.y * 128;

    float acc[4][8][4];
    gemm_f16_mainloop(g_ctx + (size_t)rowBase * KDIM,
                      g_Wo + (size_t)n0 * KDIM,
                      uA, uB, acc, tid, wm, wn);

    #pragma unroll
    for (int mt = 0; mt < 4; ++mt) {
        int m0 = rowBase + wm * 64 + mt * 16 + g;
        #pragma unroll
        for (int nt = 0; nt < 8; ++nt) {
            int n = n0 + wn * 64 + nt * 8 + 2 * q;
            float2 bias = *reinterpret_cast<const float2*>(&bo[n]);
            float2 v0 = {acc[mt][nt][0] + bias.x, acc[mt][nt][1] + bias.y};
            float2 v1 = {acc[mt][nt][2] + bias.x, acc[mt][nt][3] + bias.y};
            *reinterpret_cast<float2*>(&out[(size_t)m0 * DOUT + n])       = v0;
            *reinterpret_cast<float2*>(&out[(size_t)(m0 + 8) * DOUT + n]) = v1;
        }
    }
}

// ---------------------------------------------------------------------------
// Kernel 2: causal flash attention (exact R15 champion).
// f16 MMA, 4-stage cp.async, 1 sync/chunk; final-diagonal lower warps skip.
// ---------------------------------------------------------------------------
#define KPADH 72
#define KSTGB (64 * KPADH * 2)    // 9216 bytes per stage per matrix

#define FLASH_ISSUE(c, stage) do {                                           \
    const __half* Kp_ = g_K + ((size_t)bh * S_ + (c) * 64) * HD_;            \
    const __half* Vp_ = g_V + ((size_t)bh * S_ + (c) * 64) * HD_;            \
    _Pragma("unroll")                                                        \
    for (int i_ = 0; i_ < 2; ++i_) {                                         \
        int f_ = tid + i_ * 256, row_ = f_ >> 3, k8_ = f_ & 7;               \
        uint32_t so_ = (uint32_t)(stage) * KSTGB +                           \
                       (uint32_t)(row_ * KPADH + k8_ * 8) * 2u;              \
        cp16(uK + so_, Kp_ + row_ * HD_ + k8_ * 8);                          \
        cp16(uV + so_, Vp_ + row_ * HD_ + k8_ * 8);                          \
    }                                                                        \
    CP_COMMIT();                                                             \
} while (0)

__global__ __launch_bounds__(256, 2) void flash_tc_kernel()
{
    extern __shared__ uint32_t dyn[];
    const uint32_t uK = smem_u32(dyn);
    const uint32_t uV = uK + 4 * KSTGB;

    const int tid  = threadIdx.x;
    const int wid  = tid >> 5, lane = tid & 31;
    const int g    = lane >> 2, q = lane & 3;
    const int qt   = (int)gridDim.x - 1 - (int)blockIdx.x;  // big tiles first
    const int bh   = blockIdx.y;
    const int mrow0 = qt * 128 + wid * 16 + g;

    const uint32_t baseK = uK +
        (uint32_t)((lane & 15) * KPADH + (lane >> 4) * 8) * 2u;
    const uint32_t baseV = uV +
        (uint32_t)((lane & 15) * KPADH + (lane >> 4) * 8) * 2u;

    // Q A-fragments (g_Q already scaled by 0.125*log2e, f16)
    uint32_t qf[4][4];
    {
        const __half* Q0 = g_Q + ((size_t)bh * S_ + mrow0) * HD_;
        const __half* Q1 = Q0 + (size_t)8 * HD_;
        #pragma unroll
        for (int ks = 0; ks < 4; ++ks) {
            qf[ks][0] = *reinterpret_cast<const uint32_t*>(Q0 + ks * 16 + 2 * q);
            qf[ks][1] = *reinterpret_cast<const uint32_t*>(Q1 + ks * 16 + 2 * q);
            qf[ks][2] = *reinterpret_cast<const uint32_t*>(Q0 + ks * 16 + 8 + 2 * q);
            qf[ks][3] = *reinterpret_cast<const uint32_t*>(Q1 + ks * 16 + 8 + 2 * q);
        }
    }

    float o[8][4];
    #pragma unroll
    for (int nt = 0; nt < 8; ++nt)
        #pragma unroll
        for (int j = 0; j < 4; ++j) o[nt][j] = 0.0f;
    float mA = -1e30f, mB = -1e30f, lA = 0.0f, lB = 0.0f;

    const int nch = 2 * qt + 2;
    FLASH_ISSUE(0, 0);
    FLASH_ISSUE(1, 1);
    if (nch > 2) FLASH_ISSUE(2, 2);

    for (int c = 0; c < nch; ++c) {
        if (c + 2 < nch)      CP_WAIT(2);
        else if (c + 1 < nch) CP_WAIT(1);
        else                  CP_WAIT(0);
        __syncthreads();
        if (c + 3 < nch) FLASH_ISSUE(c + 3, (c + 3) & 3);

        // warp-uniform skip: final diagonal chunk, lower warp-group fully masked
        if (c == 2 * qt + 1 && wid < 4) continue;

        const uint32_t stg = (uint32_t)(c & 3) * KSTGB;

        // S = Q K^T  (log2 units)
        float s[8][4];
        #pragma unroll
        for (int nt = 0; nt < 8; ++nt)
            #pragma unroll
            for (int j = 0; j < 4; ++j) s[nt][j] = 0.0f;
        #pragma unroll
        for (int ks = 0; ks < 4; ++ks) {
            #pragma unroll
            for (int ntp = 0; ntp < 4; ++ntp) {
                uint32_t r0, r1, r2, r3;
                ldsm_x4(baseK + stg + (uint32_t)(ntp * 16 * KPADH + ks * 16) * 2u,
                        r0, r1, r2, r3);
                mma_f16(s[2 * ntp],     qf[ks][0], qf[ks][1], qf[ks][2], qf[ks][3], r0, r2);
                mma_f16(s[2 * ntp + 1], qf[ks][0], qf[ks][1], qf[ks][2], qf[ks][3], r1, r3);
            }
        }

        if (c >= 2 * qt) {   // causal mask, last two chunks only
            int kb = c * 64;
            #pragma unroll
            for (int nt = 0; nt < 8; ++nt) {
                int col = kb + nt * 8 + 2 * q;
                if (col     > mrow0)     s[nt][0] = -1e30f;
                if (col + 1 > mrow0)     s[nt][1] = -1e30f;
                if (col     > mrow0 + 8) s[nt][2] = -1e30f;
                if (col + 1 > mrow0 + 8) s[nt][3] = -1e30f;
            }
        }

        // online softmax (max quad-reduce; l stays per-thread partial)
        float tmA = -1e30f, tmB = -1e30f;
        #pragma unroll
        for (int nt = 0; nt < 8; ++nt) {
            tmA = fmaxf(tmA, fmaxf(s[nt][0], s[nt][1]));
            tmB = fmaxf(tmB, fmaxf(s[nt][2], s[nt][3]));
        }
        tmA = fmaxf(tmA, __shfl_xor_sync(0xffffffffu, tmA, 1));
        tmA = fmaxf(tmA, __shfl_xor_sync(0xffffffffu, tmA, 2));
        tmB = fmaxf(tmB, __shfl_xor_sync(0xffffffffu, tmB, 1));
        tmB = fmaxf(tmB, __shfl_xor_sync(0xffffffffu, tmB, 2));
        float mnA = fmaxf(mA, tmA), mnB = fmaxf(mB, tmB);
        float corrA = fexp2(mA - mnA), corrB = fexp2(mB - mnB);
        lA *= corrA; lB *= corrB;
        #pragma unroll
        for (int nt = 0; nt < 8; ++nt) {
            o[nt][0] *= corrA; o[nt][1] *= corrA;
            o[nt][2] *= corrB; o[nt][3] *= corrB;
        }

        #pragma unroll
        for (int nt = 0; nt < 8; ++nt) {
            float p0 = fexp2(s[nt][0] - mnA);
            float p1 = fexp2(s[nt][1] - mnA);
            float p2 = fexp2(s[nt][2] - mnB);
            float p3 = fexp2(s[nt][3] - mnB);
            lA += p0 + p1; lB += p2 + p3;
            s[nt][0] = p0; s[nt][1] = p1; s[nt][2] = p2; s[nt][3] = p3;
        }
        mA = mnA; mB = mnB;

        // pack P C-frags -> A-frags (FA2 identity, zero shuffles)
        uint32_t pa[4][4];
        #pragma unroll
        for (int kk = 0; kk < 4; ++kk) {
            pa[kk][0] = pack_h2(s[2 * kk][0],     s[2 * kk][1]);
            pa[kk][1] = pack_h2(s[2 * kk][2],     s[2 * kk][3]);
            pa[kk][2] = pack_h2(s[2 * kk + 1][0], s[2 * kk + 1][1]);
            pa[kk][3] = pack_h2(s[2 * kk + 1][2], s[2 * kk + 1][3]);
        }

        // O += P V   (V B-frags via ldmatrix.trans from [key][hd])
        #pragma unroll
        for (int ks = 0; ks < 4; ++ks) {
            #pragma unroll
            for (int hdp = 0; hdp < 4; ++hdp) {
                uint32_t r0, r1, r2, r3;
                ldsm_x4_t(baseV + stg + (uint32_t)(ks * 16 * KPADH + hdp * 16) * 2u,
                          r0, r1, r2, r3);
                mma_f16(o[2 * hdp],     pa[ks][0], pa[ks][1], pa[ks][2], pa[ks][3], r0, r1);
                mma_f16(o[2 * hdp + 1], pa[ks][0], pa[ks][1], pa[ks][2], pa[ks][3], r2, r3);
            }
        }
    }

    // final quad reduction of l partials
    lA += __shfl_xor_sync(0xffffffffu, lA, 1);
    lA += __shfl_xor_sync(0xffffffffu, lA, 2);
    lB += __shfl_xor_sync(0xffffffffu, lB, 1);
    lB += __shfl_xor_sync(0xffffffffu, lB, 2);

    // Normalize + write ctx (f16) in (b, s, h*64 + hd)
    const float invA = 1.0f / lA, invB = 1.0f / lB;
    const int b = bh >> 4, h = bh & 15;
    __half* base0 = g_ctx + ((size_t)(b * S_) + mrow0) * DOUT + h * HD_;
    __half* base1 = base0 + (size_t)8 * DOUT;
    #pragma unroll
    for (int nt = 0; nt < 8; ++nt) {
        int col = nt * 8 + 2 * q;
        *reinterpret_cast<uint32_t*>(base0 + col) =
            pack_h2(o[nt][0] * invA, o[nt][1] * invA);
        *reinterpret_cast<uint32_t*>(base1 + col) =
            pack_h2(o[nt][2] * invB, o[nt][3] * invB);
    }
}

// ---------------------------------------------------------------------------
extern "C" void kernel_launch(void* const* d_in, const int* in_sizes, int n_in,
                              void* d_out, int out_size)
{
    const float* x  = (const float*)d_in[0];
    const float* Wq = (const float*)d_in[1];
    const float* Wk = (const float*)d_in[2];
    const float* Wv = (const float*)d_in[3];
    const float* Wo = (const float*)d_in[4];
    const float* bo = (const float*)d_in[5];
    float* out = (float*)d_out;

    const int gemm_smem  = 4 * GSTGB;   // 73728 B  (2 stages x A,B)
    const int flash_smem = 8 * KSTGB;   // 73728 B  (4 stages x K,V)
    cudaFuncSetAttribute(qkv_tc_kernel,
        cudaFuncAttributeMaxDynamicSharedMemorySize, gemm_smem);
    cudaFuncSetAttribute(oproj_tc_kernel,
        cudaFuncAttributeMaxDynamicSharedMemorySize, gemm_smem);
    cudaFuncSetAttribute(flash_tc_kernel,
        cudaFuncAttributeMaxDynamicSharedMemorySize, flash_smem);

    prep_kernel<<<CVTBLK + 3072, 256>>>(x, Wq, Wk, Wv, Wo);
    qkv_tc_kernel<<<dim3(64, 24), 128, gemm_smem>>>();
    flash_tc_kernel<<<dim3(16, 64), 256, flash_smem>>>();
    oproj_tc_kernel<<<dim3(64, 8), 128, gemm_smem>>>(bo, out);
}

// round 17
// speedup vs baseline: 1.0804x; 1.0804x over previous
#include <cuda_runtime.h>
#include <cuda_fp16.h>
#include <cstdint>

#define B_   4
#define S_   2048
#define DIN  1024
#define DOUT 1024
#define H_   16
#define HD_  64
#define KDIM 1024

// ---------------------------------------------------------------------------
// Scratch (module-scope device arrays: allowed; no runtime allocation)
// ---------------------------------------------------------------------------
__device__ __half g_Q[B_ * H_ * S_ * HD_];   // (b,h,s,hd), pre-scaled by 0.125*log2e
__device__ __half g_K[B_ * H_ * S_ * HD_];   // (b,h,s,hd)
__device__ __half g_V[B_ * H_ * S_ * HD_];   // (b,h,s,hd)
__device__ __half g_ctx[B_ * S_ * DOUT];     // (b,s,d)
__device__ __half g_Wf[3 * DIN * DOUT];      // Wq,Wk,Wv NATIVE [k][n], f16
__device__ __half g_X [B_ * S_ * DIN];       // x, f16
__device__ __half g_Wo[DOUT * DOUT];         // Wo [n][k], f16

// ---------------------------------------------------------------------------
// helpers
// ---------------------------------------------------------------------------
__device__ __forceinline__ uint32_t pack_h2(float lo, float hi) {
    uint32_t d;
    asm("cvt.rn.f16x2.f32 %0, %1, %2;" : "=r"(d) : "f"(hi), "f"(lo));
    return d;
}
__device__ __forceinline__ float fexp2(float x) {
    float y;
    asm("ex2.approx.f32 %0, %1;" : "=f"(y) : "f"(x));
    return y;
}
__device__ __forceinline__ uint32_t smem_u32(const void* p) {
    uint32_t a;
    asm("{ .reg .u64 t; cvta.to.shared.u64 t, %1; cvt.u32.u64 %0, t; }"
        : "=r"(a) : "l"(p));
    return a;
}
__device__ __forceinline__ void cp16(uint32_t dst, const void* src) {
    asm volatile("cp.async.cg.shared.global [%0], [%1], 16;"
                 :: "r"(dst), "l"(src) : "memory");
}
#define CP_COMMIT() asm volatile("cp.async.commit_group;" ::: "memory")
#define CP_WAIT(n)  asm volatile("cp.async.wait_group %0;" :: "n"(n) : "memory")

__device__ __forceinline__ void ldsm_x4(uint32_t addr,
    uint32_t& r0, uint32_t& r1, uint32_t& r2, uint32_t& r3)
{
    asm volatile("ldmatrix.sync.aligned.m8n8.x4.shared.b16 {%0,%1,%2,%3}, [%4];"
        : "=r"(r0), "=r"(r1), "=r"(r2), "=r"(r3) : "r"(addr));
}
__device__ __forceinline__ void ldsm_x4_t(uint32_t addr,
    uint32_t& r0, uint32_t& r1, uint32_t& r2, uint32_t& r3)
{
    asm volatile("ldmatrix.sync.aligned.m8n8.x4.trans.shared.b16 {%0,%1,%2,%3}, [%4];"
        : "=r"(r0), "=r"(r1), "=r"(r2), "=r"(r3) : "r"(addr));
}

// D += A*B, m16n8k16 f16 inputs, fp32 accumulate
__device__ __forceinline__ void mma_f16(float* d,
    uint32_t a0, uint32_t a1, uint32_t a2, uint32_t a3,
    uint32_t b0, uint32_t b1)
{
    asm volatile(
        "mma.sync.aligned.m16n8k16.row.col.f32.f16.f16.f32 "
        "{%0,%1,%2,%3}, {%4,%5,%6,%7}, {%8,%9}, {%0,%1,%2,%3};"
        : "+f"(d[0]), "+f"(d[1]), "+f"(d[2]), "+f"(d[3])
        : "r"(a0), "r"(a1), "r"(a2), "r"(a3), "r"(b0), "r"(b1));
}

// ---------------------------------------------------------------------------
// Kernel P: prep — pure f16 conversion, no transposes.
// i in [0,XF4): x -> g_X; [XF4,XF4+WF4): Wo -> g_Wo;
// rest: Wq/Wk/Wv -> g_Wf (native [k][n] layout).
// ---------------------------------------------------------------------------
#define XF4  (B_ * S_ * DIN / 4)        // 2097152
#define WF4  (DOUT * DOUT / 4)          // 262144
#define PREPBLK ((XF4 + 4 * WF4) / 256) // 12288
__global__ __launch_bounds__(256) void prep_kernel(
    const float* __restrict__ x,  const float* __restrict__ Wq,
    const float* __restrict__ Wk, const float* __restrict__ Wv,
    const float* __restrict__ Wo)
{
    int i = blockIdx.x * 256 + threadIdx.x;
    const float* src;
    __half* dst;
    int j;
    if (i < XF4) {
        src = x; dst = g_X; j = i;
    } else if (i < XF4 + WF4) {
        src = Wo; dst = g_Wo; j = i - XF4;
    } else {
        int t = i - XF4 - WF4;
        int z = t / WF4;
        j = t - z * WF4;
        src = (z == 0) ? Wq : (z == 1) ? Wk : Wv;
        dst = g_Wf + (size_t)z * DIN * DOUT;
    }
    float4 v = *reinterpret_cast<const float4*>(src + (size_t)j * 4);
    uint2 r = {pack_h2(v.x, v.y), pack_h2(v.z, v.w)};
    reinterpret_cast<uint2*>(dst)[j] = r;
}

// ---------------------------------------------------------------------------
// GEMM f16: C[128x128] = A[128xK] * op(B), fp32 accum.  (R13/R15 champion cfg)
// 512 threads, 16 warps (4m x 4n), warp tile 32x32 (8 warps/SMSP at 2 CTAs).
// BK=64, 2-stage cp.async, ONE __syncthreads per chunk (issue after sync).
// BT=0: B stored [n][k] (rows n, GPADH pad), non-trans ldsm.
// BT=1: B stored [k][n] (rows k, BPADT pad), trans ldsm (flash-V pattern).
// ---------------------------------------------------------------------------
#define GPADH 72
#define ASTGB (128 * GPADH * 2)    // 18432 B / A stage
#define BPADT 136
#define BSTGT (64 * BPADT * 2)     // 17408 B / B stage (trans layout)
#define NCH64 (KDIM / 64)          // 16 chunks

// non-trans issue: A rows 0..127 (m), B rows 0..127 (n), both k-chunked
#define GEMM_ISSUE_N(ch, stage) do {                                         \
    _Pragma("unroll")                                                        \
    for (int i_ = 0; i_ < 2; ++i_) {                                         \
        int f_ = tid + i_ * 512, row_ = f_ >> 3, k8_ = f_ & 7;               \
        uint32_t off_ = (uint32_t)(stage) * ASTGB +                          \
                        (uint32_t)(row_ * GPADH + k8_ * 8) * 2u;             \
        cp16(uA + off_, Asrc + (size_t)row_ * KDIM + (ch) * 64 + k8_ * 8);   \
        cp16(uB + off_, Bsrc + (size_t)row_ * KDIM + (ch) * 64 + k8_ * 8);   \
    }                                                                        \
    CP_COMMIT();                                                             \
} while (0)

// trans issue: A as above; B rows = k (64), 128 n-cols (256B) per row
#define GEMM_ISSUE_T(ch, stage) do {                                         \
    _Pragma("unroll")                                                        \
    for (int i_ = 0; i_ < 2; ++i_) {                                         \
        int f_ = tid + i_ * 512, rowa_ = f_ >> 3, k8_ = f_ & 7;              \
        cp16(uA + (uint32_t)(stage) * ASTGB +                                \
                  (uint32_t)(rowa_ * GPADH + k8_ * 8) * 2u,                  \
             Asrc + (size_t)rowa_ * KDIM + (ch) * 64 + k8_ * 8);             \
        int rowb_ = f_ >> 4, n16_ = f_ & 15;                                 \
        cp16(uB + (uint32_t)(stage) * BSTGT +                                \
                  (uint32_t)(rowb_ * BPADT + n16_ * 8) * 2u,                 \
             Bsrc + (size_t)((ch) * 64 + rowb_) * DOUT + n16_ * 8);          \
    }                                                                        \
    CP_COMMIT();                                                             \
} while (0)

template <int BT>
__device__ __forceinline__ void gemm_f16_mainloop(
    const __half* __restrict__ Asrc, const __half* __restrict__ Bsrc,
    uint32_t uA, uint32_t uB, float acc[2][4][4], int tid, int wm, int wn)
{
    const int lane = tid & 31;
    #pragma unroll
    for (int mt = 0; mt < 2; ++mt)
        #pragma unroll
        for (int nt = 0; nt < 4; ++nt)
            #pragma unroll
            for (int j = 0; j < 4; ++j) acc[mt][nt][j] = 0.0f;

    const uint32_t baseA = uA +
        (uint32_t)((wm * 32 + (lane & 15)) * GPADH + (lane >> 4) * 8) * 2u;
    const uint32_t baseBn = uB +
        (uint32_t)((wn * 32 + (lane & 15)) * GPADH + (lane >> 4) * 8) * 2u;
    const uint32_t baseBt = uB +
        (uint32_t)((lane & 15) * BPADT + (lane >> 4) * 8 + wn * 32) * 2u;

    if (BT) GEMM_ISSUE_T(0, 0); else GEMM_ISSUE_N(0, 0);
    for (int ch = 0; ch < NCH64; ++ch) {
        CP_WAIT(0);
        __syncthreads();
        if (ch + 1 < NCH64) {
            if (BT) GEMM_ISSUE_T(ch + 1, (ch + 1) & 1);
            else    GEMM_ISSUE_N(ch + 1, (ch + 1) & 1);
        }

        const uint32_t stgA = (uint32_t)(ch & 1) * ASTGB;
        const uint32_t stgB = (uint32_t)(ch & 1) * (BT ? BSTGT : ASTGB);
        #pragma unroll
        for (int ks = 0; ks < 4; ++ks) {
            uint32_t a[2][4], b[4][2];
            #pragma unroll
            for (int mt = 0; mt < 2; ++mt)
                ldsm_x4(baseA + stgA + (uint32_t)(mt * 16 * GPADH + ks * 16) * 2u,
                        a[mt][0], a[mt][1], a[mt][2], a[mt][3]);
            if (BT) {
                #pragma unroll
                for (int ntp = 0; ntp < 2; ++ntp) {
                    uint32_t r0, r1, r2, r3;
                    ldsm_x4_t(baseBt + stgB +
                              (uint32_t)(ks * 16 * BPADT + ntp * 16) * 2u,
                              r0, r1, r2, r3);
                    b[2 * ntp][0] = r0; b[2 * ntp][1] = r1;     // n+0..7
                    b[2 * ntp + 1][0] = r2; b[2 * ntp + 1][1] = r3; // n+8..15
                }
            } else {
                #pragma unroll
                for (int ntp = 0; ntp < 2; ++ntp) {
                    uint32_t r0, r1, r2, r3;
                    ldsm_x4(baseBn + stgB +
                            (uint32_t)(ntp * 16 * GPADH + ks * 16) * 2u,
                            r0, r1, r2, r3);
                    b[2 * ntp][0] = r0; b[2 * ntp][1] = r2;
                    b[2 * ntp + 1][0] = r1; b[2 * ntp + 1][1] = r3;
                }
            }
            #pragma unroll
            for (int mt = 0; mt < 2; ++mt)
                #pragma unroll
                for (int nt = 0; nt < 4; ++nt)
                    mma_f16(acc[mt][nt], a[mt][0], a[mt][1], a[mt][2], a[mt][3],
                            b[nt][0], b[nt][1]);
        }
    }
}

// ---------------------------------------------------------------------------
// Kernel 1: QKV projection.  grid (64, 24), 512 threads, dyn smem.
// B = native [k][n] weights via trans ldsm (no transpose prep needed).
// ---------------------------------------------------------------------------
__global__ __launch_bounds__(512, 2) void qkv_tc_kernel()
{
    extern __shared__ uint32_t dyn[];
    const uint32_t uA = smem_u32(dyn);
    const uint32_t uB = uA + 2 * ASTGB;

    const int tid = threadIdx.x;
    const int wid = tid >> 5, lane = tid & 31;
    const int g = lane >> 2, q = lane & 3;
    const int wm = wid >> 2, wn = wid & 3;

    const int rowBase = blockIdx.x * 128;
    const int n0glob  = blockIdx.y * 128;
    const int w       = n0glob >> 10;
    const int nw      = n0glob & 1023;

    float acc[2][4][4];
    gemm_f16_mainloop<1>(g_X + (size_t)rowBase * KDIM,
                         g_Wf + (size_t)w * (DIN * DOUT) + nw,
                         uA, uB, acc, tid, wm, wn);

    __half* obuf = (w == 0) ? g_Q : (w == 1) ? g_K : g_V;
    const float scale = (w == 0) ? 0.125f * 1.4426950408889634f : 1.0f;
    #pragma unroll
    for (int mt = 0; mt < 2; ++mt) {
        int m0 = rowBase + wm * 32 + mt * 16 + g;
        int b0 = m0 >> 11, s0 = m0 & 2047;
        int m1 = m0 + 8;
        int b1 = m1 >> 11, s1 = m1 & 2047;
        #pragma unroll
        for (int nt = 0; nt < 4; ++nt) {
            int n  = nw + wn * 32 + nt * 8 + 2 * q;
            int h  = n >> 6, hd = n & 63;
            uint32_t v0 = pack_h2(acc[mt][nt][0] * scale, acc[mt][nt][1] * scale);
            uint32_t v1 = pack_h2(acc[mt][nt][2] * scale, acc[mt][nt][3] * scale);
            *reinterpret_cast<uint32_t*>(
                &obuf[(((size_t)(b0 * H_ + h) * S_) + s0) * HD_ + hd]) = v0;
            *reinterpret_cast<uint32_t*>(
                &obuf[(((size_t)(b1 * H_ + h) * S_) + s1) * HD_ + hd]) = v1;
        }
    }
}

// ---------------------------------------------------------------------------
// Kernel 3: output projection.  out = ctx @ Wo^T + bo (fp32 out).  grid (64, 8).
// Wo is [n][k] native -> non-trans path (BT=0).
// ---------------------------------------------------------------------------
__global__ __launch_bounds__(512, 2) void oproj_tc_kernel(
    const float* __restrict__ bo, float* __restrict__ out)
{
    extern __shared__ uint32_t dyn[];
    const uint32_t uA = smem_u32(dyn);
    const uint32_t uB = uA + 2 * ASTGB;

    const int tid = threadIdx.x;
    const int wid = tid >> 5, lane = tid & 31;
    const int g = lane >> 2, q = lane & 3;
    const int wm = wid >> 2, wn = wid & 3;

    const int rowBase = blockIdx.x * 128;
    const int n0      = blockIdx.y * 128;

    float acc[2][4][4];
    gemm_f16_mainloop<0>(g_ctx + (size_t)rowBase * KDIM,
                         g_Wo + (size_t)n0 * KDIM,
                         uA, uB, acc, tid, wm, wn);

    #pragma unroll
    for (int mt = 0; mt < 2; ++mt) {
        int m0 = rowBase + wm * 32 + mt * 16 + g;
        #pragma unroll
        for (int nt = 0; nt < 4; ++nt) {
            int n = n0 + wn * 32 + nt * 8 + 2 * q;
            float2 bias = *reinterpret_cast<const float2*>(&bo[n]);
            float2 v0 = {acc[mt][nt][0] + bias.x, acc[mt][nt][1] + bias.y};
            float2 v1 = {acc[mt][nt][2] + bias.x, acc[mt][nt][3] + bias.y};
            *reinterpret_cast<float2*>(&out[(size_t)m0 * DOUT + n])       = v0;
            *reinterpret_cast<float2*>(&out[(size_t)(m0 + 8) * DOUT + n]) = v1;
        }
    }
}

// ---------------------------------------------------------------------------
// Kernel 2: causal flash attention (exact R15 champion).
// f16 MMA, 4-stage cp.async, 1 sync/chunk; final-diagonal lower warps skip.
// ---------------------------------------------------------------------------
#define KPADH 72
#define KSTGB (64 * KPADH * 2)    // 9216 bytes per stage per matrix

#define FLASH_ISSUE(c, stage) do {                                           \
    const __half* Kp_ = g_K + ((size_t)bh * S_ + (c) * 64) * HD_;            \
    const __half* Vp_ = g_V + ((size_t)bh * S_ + (c) * 64) * HD_;            \
    _Pragma("unroll")                                                        \
    for (int i_ = 0; i_ < 2; ++i_) {                                         \
        int f_ = tid + i_ * 256, row_ = f_ >> 3, k8_ = f_ & 7;               \
        uint32_t so_ = (uint32_t)(stage) * KSTGB +                           \
                       (uint32_t)(row_ * KPADH + k8_ * 8) * 2u;              \
        cp16(uK + so_, Kp_ + row_ * HD_ + k8_ * 8);                          \
        cp16(uV + so_, Vp_ + row_ * HD_ + k8_ * 8);                          \
    }                                                                        \
    CP_COMMIT();                                                             \
} while (0)

__global__ __launch_bounds__(256, 2) void flash_tc_kernel()
{
    extern __shared__ uint32_t dyn[];
    const uint32_t uK = smem_u32(dyn);
    const uint32_t uV = uK + 4 * KSTGB;

    const int tid  = threadIdx.x;
    const int wid  = tid >> 5, lane = tid & 31;
    const int g    = lane >> 2, q = lane & 3;
    const int qt   = (int)gridDim.x - 1 - (int)blockIdx.x;  // big tiles first
    const int bh   = blockIdx.y;
    const int mrow0 = qt * 128 + wid * 16 + g;

    const uint32_t baseK = uK +
        (uint32_t)((lane & 15) * KPADH + (lane >> 4) * 8) * 2u;
    const uint32_t baseV = uV +
        (uint32_t)((lane & 15) * KPADH + (lane >> 4) * 8) * 2u;

    // Q A-fragments (g_Q already scaled by 0.125*log2e, f16)
    uint32_t qf[4][4];
    {
        const __half* Q0 = g_Q + ((size_t)bh * S_ + mrow0) * HD_;
        const __half* Q1 = Q0 + (size_t)8 * HD_;
        #pragma unroll
        for (int ks = 0; ks < 4; ++ks) {
            qf[ks][0] = *reinterpret_cast<const uint32_t*>(Q0 + ks * 16 + 2 * q);
            qf[ks][1] = *reinterpret_cast<const uint32_t*>(Q1 + ks * 16 + 2 * q);
            qf[ks][2] = *reinterpret_cast<const uint32_t*>(Q0 + ks * 16 + 8 + 2 * q);
            qf[ks][3] = *reinterpret_cast<const uint32_t*>(Q1 + ks * 16 + 8 + 2 * q);
        }
    }

    float o[8][4];
    #pragma unroll
    for (int nt = 0; nt < 8; ++nt)
        #pragma unroll
        for (int j = 0; j < 4; ++j) o[nt][j] = 0.0f;
    float mA = -1e30f, mB = -1e30f, lA = 0.0f, lB = 0.0f;

    const int nch = 2 * qt + 2;
    FLASH_ISSUE(0, 0);
    FLASH_ISSUE(1, 1);
    if (nch > 2) FLASH_ISSUE(2, 2);

    for (int c = 0; c < nch; ++c) {
        if (c + 2 < nch)      CP_WAIT(2);
        else if (c + 1 < nch) CP_WAIT(1);
        else                  CP_WAIT(0);
        __syncthreads();
        if (c + 3 < nch) FLASH_ISSUE(c + 3, (c + 3) & 3);

        // warp-uniform skip: final diagonal chunk, lower warp-group fully masked
        if (c == 2 * qt + 1 && wid < 4) continue;

        const uint32_t stg = (uint32_t)(c & 3) * KSTGB;

        // S = Q K^T  (log2 units)
        float s[8][4];
        #pragma unroll
        for (int nt = 0; nt < 8; ++nt)
            #pragma unroll
            for (int j = 0; j < 4; ++j) s[nt][j] = 0.0f;
        #pragma unroll
        for (int ks = 0; ks < 4; ++ks) {
            #pragma unroll
            for (int ntp = 0; ntp < 4; ++ntp) {
                uint32_t r0, r1, r2, r3;
                ldsm_x4(baseK + stg + (uint32_t)(ntp * 16 * KPADH + ks * 16) * 2u,
                        r0, r1, r2, r3);
                mma_f16(s[2 * ntp],     qf[ks][0], qf[ks][1], qf[ks][2], qf[ks][3], r0, r2);
                mma_f16(s[2 * ntp + 1], qf[ks][0], qf[ks][1], qf[ks][2], qf[ks][3], r1, r3);
            }
        }

        if (c >= 2 * qt) {   // causal mask, last two chunks only
            int kb = c * 64;
            #pragma unroll
            for (int nt = 0; nt < 8; ++nt) {
                int col = kb + nt * 8 + 2 * q;
                if (col     > mrow0)     s[nt][0] = -1e30f;
                if (col + 1 > mrow0)     s[nt][1] = -1e30f;
                if (col     > mrow0 + 8) s[nt][2] = -1e30f;
                if (col + 1 > mrow0 + 8) s[nt][3] = -1e30f;
            }
        }

        // online softmax (max quad-reduce; l stays per-thread partial)
        float tmA = -1e30f, tmB = -1e30f;
        #pragma unroll
        for (int nt = 0; nt < 8; ++nt) {
            tmA = fmaxf(tmA, fmaxf(s[nt][0], s[nt][1]));
            tmB = fmaxf(tmB, fmaxf(s[nt][2], s[nt][3]));
        }
        tmA = fmaxf(tmA, __shfl_xor_sync(0xffffffffu, tmA, 1));
        tmA = fmaxf(tmA, __shfl_xor_sync(0xffffffffu, tmA, 2));
        tmB = fmaxf(tmB, __shfl_xor_sync(0xffffffffu, tmB, 1));
        tmB = fmaxf(tmB, __shfl_xor_sync(0xffffffffu, tmB, 2));
        float mnA = fmaxf(mA, tmA), mnB = fmaxf(mB, tmB);
        float corrA = fexp2(mA - mnA), corrB = fexp2(mB - mnB);
        lA *= corrA; lB *= corrB;
        #pragma unroll
        for (int nt = 0; nt < 8; ++nt) {
            o[nt][0] *= corrA; o[nt][1] *= corrA;
            o[nt][2] *= corrB; o[nt][3] *= corrB;
        }

        #pragma unroll
        for (int nt = 0; nt < 8; ++nt) {
            float p0 = fexp2(s[nt][0] - mnA);
            float p1 = fexp2(s[nt][1] - mnA);
            float p2 = fexp2(s[nt][2] - mnB);
            float p3 = fexp2(s[nt][3] - mnB);
            lA += p0 + p1; lB += p2 + p3;
            s[nt][0] = p0; s[nt][1] = p1; s[nt][2] = p2; s[nt][3] = p3;
        }
        mA = mnA; mB = mnB;

        // pack P C-frags -> A-frags (FA2 identity, zero shuffles)
        uint32_t pa[4][4];
        #pragma unroll
        for (int kk = 0; kk < 4; ++kk) {
            pa[kk][0] = pack_h2(s[2 * kk][0],     s[2 * kk][1]);
            pa[kk][1] = pack_h2(s[2 * kk][2],     s[2 * kk][3]);
            pa[kk][2] = pack_h2(s[2 * kk + 1][0], s[2 * kk + 1][1]);
            pa[kk][3] = pack_h2(s[2 * kk + 1][2], s[2 * kk + 1][3]);
        }

        // O += P V   (V B-frags via ldmatrix.trans from [key][hd])
        #pragma unroll
        for (int ks = 0; ks < 4; ++ks) {
            #pragma unroll
            for (int hdp = 0; hdp < 4; ++hdp) {
                uint32_t r0, r1, r2, r3;
                ldsm_x4_t(baseV + stg + (uint32_t)(ks * 16 * KPADH + hdp * 16) * 2u,
                          r0, r1, r2, r3);
                mma_f16(o[2 * hdp],     pa[ks][0], pa[ks][1], pa[ks][2], pa[ks][3], r0, r1);
                mma_f16(o[2 * hdp + 1], pa[ks][0], pa[ks][1], pa[ks][2], pa[ks][3], r2, r3);
            }
        }
    }

    // final quad reduction of l partials
    lA += __shfl_xor_sync(0xffffffffu, lA, 1);
    lA += __shfl_xor_sync(0xffffffffu, lA, 2);
    lB += __shfl_xor_sync(0xffffffffu, lB, 1);
    lB += __shfl_xor_sync(0xffffffffu, lB, 2);

    // Normalize + write ctx (f16) in (b, s, h*64 + hd)
    const float invA = 1.0f / lA, invB = 1.0f / lB;
    const int b = bh >> 4, h = bh & 15;
    __half* base0 = g_ctx + ((size_t)(b * S_) + mrow0) * DOUT + h * HD_;
    __half* base1 = base0 + (size_t)8 * DOUT;
    #pragma unroll
    for (int nt = 0; nt < 8; ++nt) {
        int col = nt * 8 + 2 * q;
        *reinterpret_cast<uint32_t*>(base0 + col) =
            pack_h2(o[nt][0] * invA, o[nt][1] * invA);
        *reinterpret_cast<uint32_t*>(base1 + col) =
            pack_h2(o[nt][2] * invB, o[nt][3] * invB);
    }
}

// ---------------------------------------------------------------------------
extern "C" void kernel_launch(void* const* d_in, const int* in_sizes, int n_in,
                              void* d_out, int out_size)
{
    const float* x  = (const float*)d_in[0];
    const float* Wq = (const float*)d_in[1];
    const float* Wk = (const float*)d_in[2];
    const float* Wv = (const float*)d_in[3];
    const float* Wo = (const float*)d_in[4];
    const float* bo = (const float*)d_in[5];
    float* out = (float*)d_out;

    const int qkv_smem   = 2 * ASTGB + 2 * BSTGT;  // 71680 B
    const int oproj_smem = 4 * ASTGB;              // 73728 B
    const int flash_smem = 8 * KSTGB;              // 73728 B
    cudaFuncSetAttribute(qkv_tc_kernel,
        cudaFuncAttributeMaxDynamicSharedMemorySize, qkv_smem);
    cudaFuncSetAttribute(oproj_tc_kernel,
        cudaFuncAttributeMaxDynamicSharedMemorySize, oproj_smem);
    cudaFuncSetAttribute(flash_tc_kernel,
        cudaFuncAttributeMaxDynamicSharedMemorySize, flash_smem);

    prep_kernel<<<PREPBLK, 256>>>(x, Wq, Wk, Wv, Wo);
    qkv_tc_kernel<<<dim3(64, 24), 512, qkv_smem>>>();
    flash_tc_kernel<<<dim3(16, 64), 256, flash_smem>>>();
    oproj_tc_kernel<<<dim3(64, 8), 512, oproj_smem>>>(bo, out);
}